// round 1
// baseline (speedup 1.0000x reference)
#include <cuda_runtime.h>
#include <cuda_bf16.h>
#include <math.h>

// ---------------------------------------------------------------------------
// Problem constants (fixed shapes)
// ---------------------------------------------------------------------------
#define B_      8
#define LQ      3072          // 3*32*32
#define C_      768
#define HF      64
#define WF      64
#define LIN     (HF*WF)       // 4096
#define NH      6
#define NP      4
#define DH      128           // C/NH
#define HID     192
#define HH      32
#define WW      32
#define NIMG    (B_*3)        // 24 depthwise images
#define EPSLN   1e-6f

// ---------------------------------------------------------------------------
// Scratch (static device allocations -- allowed)
// ---------------------------------------------------------------------------
__device__ float g_qnorm[(size_t)B_*LQ*C_];     // LN(query) ; reused for LN(q2)
__device__ float g_fnorm[(size_t)B_*LIN*C_];    // LN(feat)
__device__ float g_value[(size_t)B_*LIN*C_];    // value projection
__device__ float g_attn [(size_t)B_*LQ*C_];     // deform-attn pre out-proj
__device__ float g_hid  [(size_t)B_*LQ*HID];    // fc1 out
__device__ float g_hid2 [(size_t)B_*LQ*HID];    // dwconv+gelu out

// ---------------------------------------------------------------------------
// LayerNorm: one block per row of 768, 256 threads
// ---------------------------------------------------------------------------
__global__ void __launch_bounds__(256) ln_kernel(const float* __restrict__ x,
                                                 const float* __restrict__ w,
                                                 const float* __restrict__ b,
                                                 float* __restrict__ y)
{
    int row = blockIdx.x;
    const float* xr = x + (size_t)row * C_;
    float*       yr = y + (size_t)row * C_;
    int t = threadIdx.x;

    float v[3];
    float s = 0.f, ss = 0.f;
#pragma unroll
    for (int i = 0; i < 3; i++) {
        v[i] = xr[t + i * 256];
        s  += v[i];
        ss += v[i] * v[i];
    }
    // block reduce (8 warps)
    __shared__ float rs[8], rss[8];
    int lane = t & 31, wid = t >> 5;
#pragma unroll
    for (int o = 16; o > 0; o >>= 1) {
        s  += __shfl_down_sync(0xffffffffu, s,  o);
        ss += __shfl_down_sync(0xffffffffu, ss, o);
    }
    if (lane == 0) { rs[wid] = s; rss[wid] = ss; }
    __syncthreads();
    if (wid == 0) {
        s  = (lane < 8) ? rs[lane]  : 0.f;
        ss = (lane < 8) ? rss[lane] : 0.f;
#pragma unroll
        for (int o = 4; o > 0; o >>= 1) {
            s  += __shfl_down_sync(0xffffffffu, s,  o);
            ss += __shfl_down_sync(0xffffffffu, ss, o);
        }
        if (lane == 0) { rs[0] = s; rss[0] = ss; }
    }
    __syncthreads();
    float mean = rs[0] * (1.f / C_);
    float var  = rss[0] * (1.f / C_) - mean * mean;
    float rstd = rsqrtf(var + EPSLN);
#pragma unroll
    for (int i = 0; i < 3; i++) {
        int c = t + i * 256;
        yr[c] = (v[i] - mean) * rstd * w[c] + b[c];
    }
}

// ---------------------------------------------------------------------------
// SGEMM: C = A(MxK) @ B(KxN) + bias(N) [+ res(MxN)]
// 128x128 tile, BK=8, 256 threads, 8x8 per-thread microtile
// ---------------------------------------------------------------------------
template<bool ADD_RES>
__global__ void __launch_bounds__(256) sgemm_kernel(const float* __restrict__ A,
                                                    const float* __restrict__ Bm,
                                                    const float* __restrict__ bias,
                                                    const float* __restrict__ res,
                                                    float* __restrict__ Cm,
                                                    int M, int N, int K)
{
    __shared__ float As[8][128];
    __shared__ float Bs[8][128];

    int tid = threadIdx.x;
    int tx = tid & 15;          // 0..15  -> 8 cols each
    int ty = tid >> 4;          // 0..15  -> 8 rows each
    int rowBase = blockIdx.y * 128;
    int colBase = blockIdx.x * 128;

    float acc[8][8];
#pragma unroll
    for (int i = 0; i < 8; i++)
#pragma unroll
        for (int j = 0; j < 8; j++) acc[i][j] = 0.f;

    int aRow = tid >> 1;        // 0..127
    int aK   = (tid & 1) * 4;   // 0 or 4
    int bK   = tid >> 5;        // 0..7
    int bCol = (tid & 31) * 4;  // 0..124

    const bool aval = (rowBase + aRow) < M;
    const bool bval = (colBase + bCol) < N;   // N multiple of 4, so full-vec valid iff start valid
    const float* Aptr = A + (size_t)(rowBase + aRow) * K + aK;

    for (int k0 = 0; k0 < K; k0 += 8) {
        float4 a4 = make_float4(0.f, 0.f, 0.f, 0.f);
        if (aval) a4 = *(const float4*)(Aptr + k0);
        As[aK + 0][aRow] = a4.x;
        As[aK + 1][aRow] = a4.y;
        As[aK + 2][aRow] = a4.z;
        As[aK + 3][aRow] = a4.w;

        float4 b4 = make_float4(0.f, 0.f, 0.f, 0.f);
        if (bval) b4 = *(const float4*)(Bm + (size_t)(k0 + bK) * N + colBase + bCol);
        *(float4*)&Bs[bK][bCol] = b4;

        __syncthreads();
#pragma unroll
        for (int kk = 0; kk < 8; kk++) {
            float ra[8], rb[8];
#pragma unroll
            for (int i = 0; i < 8; i++) ra[i] = As[kk][ty * 8 + i];
#pragma unroll
            for (int j = 0; j < 8; j++) rb[j] = Bs[kk][tx * 8 + j];
#pragma unroll
            for (int i = 0; i < 8; i++)
#pragma unroll
                for (int j = 0; j < 8; j++)
                    acc[i][j] = fmaf(ra[i], rb[j], acc[i][j]);
        }
        __syncthreads();
    }

#pragma unroll
    for (int i = 0; i < 8; i++) {
        int r = rowBase + ty * 8 + i;
        if (r >= M) continue;
#pragma unroll
        for (int j = 0; j < 8; j++) {
            int c = colBase + tx * 8 + j;
            if (c >= N) continue;
            float v = acc[i][j] + bias[c];
            if (ADD_RES) v += res[(size_t)r * N + c];
            Cm[(size_t)r * N + c] = v;
        }
    }
}

// ---------------------------------------------------------------------------
// Fused: sampling offsets + attn-weight logits + softmax + bilinear sampling
// one block per query row (b,lq), 128 threads
// ---------------------------------------------------------------------------
__global__ void __launch_bounds__(128) deform_kernel(const float* __restrict__ qn,
                                                     const float* __restrict__ ref,
                                                     const float* __restrict__ value,
                                                     const float* __restrict__ so_w,
                                                     const float* __restrict__ so_b,
                                                     const float* __restrict__ aw_w,
                                                     const float* __restrict__ aw_b,
                                                     float* __restrict__ out)
{
    int row = blockIdx.x;            // b*LQ + lq
    int b = row / LQ;
    int tid = threadIdx.x;

    __shared__ float q_s[C_];
    __shared__ float off_s[NH * NP * 2];
    __shared__ float aw_s[NH * NP];

    for (int i = tid; i < C_; i += 128) q_s[i] = qn[(size_t)row * C_ + i];
    __syncthreads();

    if (tid < 72) {
        float acc;
        if (tid < 48) {
            acc = so_b[tid];
            for (int k = 0; k < C_; k++) acc = fmaf(q_s[k], so_w[k * 48 + tid], acc);
            off_s[tid] = acc;
        } else {
            int o = tid - 48;
            acc = aw_b[o];
            for (int k = 0; k < C_; k++) acc = fmaf(q_s[k], aw_w[k * 24 + o], acc);
            aw_s[o] = acc;
        }
    }
    __syncthreads();

    if (tid < NH) {
        float m = -1e30f;
#pragma unroll
        for (int p = 0; p < NP; p++) m = fmaxf(m, aw_s[tid * NP + p]);
        float e[NP], ssum = 0.f;
#pragma unroll
        for (int p = 0; p < NP; p++) { e[p] = __expf(aw_s[tid * NP + p] - m); ssum += e[p]; }
        float inv = 1.f / ssum;
#pragma unroll
        for (int p = 0; p < NP; p++) aw_s[tid * NP + p] = e[p] * inv;
    }
    __syncthreads();

    float rx = ref[(size_t)row * 2 + 0] * (float)WF - 0.5f;
    float ry = ref[(size_t)row * 2 + 1] * (float)HF - 0.5f;

    const float* vbase = value + (size_t)b * LIN * C_;
    int dch = tid;   // 0..127

#pragma unroll
    for (int h = 0; h < NH; h++) {
        float acc = 0.f;
#pragma unroll
        for (int p = 0; p < NP; p++) {
            float x = rx + off_s[h * 8 + p * 2 + 0];
            float y = ry + off_s[h * 8 + p * 2 + 1];
            float aw = aw_s[h * NP + p];
            float x0f = floorf(x), y0f = floorf(y);
            int   x0 = (int)x0f,  y0 = (int)y0f;
            float wx1 = x - x0f, wy1 = y - y0f;
            float wx0 = 1.f - wx1, wy0 = 1.f - wy1;
#pragma unroll
            for (int cor = 0; cor < 4; cor++) {
                int dy = cor >> 1, dx = cor & 1;
                int xi = x0 + dx, yi = y0 + dy;
                if (xi >= 0 && xi < WF && yi >= 0 && yi < HF) {
                    float wgt = (dy ? wy1 : wy0) * (dx ? wx1 : wx0);
                    acc = fmaf(aw * wgt,
                               vbase[(size_t)(yi * WF + xi) * C_ + h * DH + dch],
                               acc);
                }
            }
        }
        out[(size_t)row * C_ + h * DH + dch] = acc;
    }
}

// ---------------------------------------------------------------------------
// Depthwise 3x3 (SAME, zero pad) + bias + exact GELU
// layout: (B*Lq, HID) row-major; image = row/1024; pixel = row%1024 = h*32+w
// ---------------------------------------------------------------------------
__global__ void __launch_bounds__(256) dwconv_gelu_kernel(const float* __restrict__ x,
                                                          const float* __restrict__ w,
                                                          const float* __restrict__ bias,
                                                          float* __restrict__ y)
{
    int e = blockIdx.x * 256 + threadIdx.x;
    const int TOT = NIMG * HH * WW * HID;
    if (e >= TOT) return;
    int ch   = e % HID;
    int rest = e / HID;
    int wc   = rest % WW;
    int hr   = (rest / WW) % HH;
    int img  = rest / (HH * WW);

    const float* xb = x + (size_t)img * HH * WW * HID;
    float acc = bias[ch];
#pragma unroll
    for (int dy = -1; dy <= 1; dy++) {
        int hh = hr + dy;
        if (hh < 0 || hh >= HH) continue;
#pragma unroll
        for (int dx = -1; dx <= 1; dx++) {
            int wwc = wc + dx;
            if (wwc < 0 || wwc >= WW) continue;
            acc = fmaf(xb[(size_t)(hh * WW + wwc) * HID + ch],
                       w[ch * 9 + (dy + 1) * 3 + (dx + 1)], acc);
        }
    }
    // exact GELU
    float g = 0.5f * acc * (1.f + erff(acc * 0.70710678118654752f));
    y[e] = g;
}

// ---------------------------------------------------------------------------
// launch
// ---------------------------------------------------------------------------
extern "C" void kernel_launch(void* const* d_in, const int* in_sizes, int n_in,
                              void* d_out, int out_size)
{
    const float* query = (const float*)d_in[0];
    const float* ref   = (const float*)d_in[1];
    const float* feat  = (const float*)d_in[2];
    // last 20 inputs are the weight tensors, robust to scalar H/W handling
    int ws = n_in - 20;
    const float* qn_w  = (const float*)d_in[ws + 0];
    const float* qn_b  = (const float*)d_in[ws + 1];
    const float* fn_w  = (const float*)d_in[ws + 2];
    const float* fn_b  = (const float*)d_in[ws + 3];
    const float* so_w  = (const float*)d_in[ws + 4];
    const float* so_b  = (const float*)d_in[ws + 5];
    const float* aw_w  = (const float*)d_in[ws + 6];
    const float* aw_b  = (const float*)d_in[ws + 7];
    const float* vp_w  = (const float*)d_in[ws + 8];
    const float* vp_b  = (const float*)d_in[ws + 9];
    const float* op_w  = (const float*)d_in[ws + 10];
    const float* op_b  = (const float*)d_in[ws + 11];
    const float* ffn_w = (const float*)d_in[ws + 12];
    const float* ffn_b = (const float*)d_in[ws + 13];
    const float* fc1_w = (const float*)d_in[ws + 14];
    const float* fc1_b = (const float*)d_in[ws + 15];
    const float* dw_w  = (const float*)d_in[ws + 16];
    const float* dw_b  = (const float*)d_in[ws + 17];
    const float* fc2_w = (const float*)d_in[ws + 18];
    const float* fc2_b = (const float*)d_in[ws + 19];

    float* out = (float*)d_out;

    float *qnorm, *fnorm, *value, *attn, *hid, *hid2;
    cudaGetSymbolAddress((void**)&qnorm, g_qnorm);
    cudaGetSymbolAddress((void**)&fnorm, g_fnorm);
    cudaGetSymbolAddress((void**)&value, g_value);
    cudaGetSymbolAddress((void**)&attn,  g_attn);
    cudaGetSymbolAddress((void**)&hid,   g_hid);
    cudaGetSymbolAddress((void**)&hid2,  g_hid2);

    const int MQ = B_ * LQ;    // 24576
    const int MF = B_ * LIN;   // 32768

    // 1) LN(query), LN(feat)
    ln_kernel<<<MQ, 256>>>(query, qn_w, qn_b, qnorm);
    ln_kernel<<<MF, 256>>>(feat, fn_w, fn_b, fnorm);

    // 2) value = LN(feat) @ vp_w + vp_b          (32768 x 768 x 768)
    {
        dim3 grid(C_ / 128, MF / 128);
        sgemm_kernel<false><<<grid, 256>>>(fnorm, vp_w, vp_b, nullptr, value, MF, C_, C_);
    }

    // 3) fused offsets + softmax + bilinear sampling
    deform_kernel<<<MQ, 128>>>(qnorm, ref, value, so_w, so_b, aw_w, aw_b, attn);

    // 4) q2 = query + attn @ op_w + op_b        -> d_out
    {
        dim3 grid(C_ / 128, MQ / 128);
        sgemm_kernel<true><<<grid, 256>>>(attn, op_w, op_b, query, out, MQ, C_, C_);
    }

    // 5) LN(q2)
    ln_kernel<<<MQ, 256>>>(out, ffn_w, ffn_b, qnorm);

    // 6) hid = LN(q2) @ fc1_w + fc1_b           (24576 x 192 x 768)
    {
        dim3 grid((HID + 127) / 128, MQ / 128);
        sgemm_kernel<false><<<grid, 256>>>(qnorm, fc1_w, fc1_b, nullptr, hid, MQ, HID, C_);
    }

    // 7) depthwise 3x3 + bias + GELU
    {
        int tot = NIMG * HH * WW * HID;
        dwconv_gelu_kernel<<<(tot + 255) / 256, 256>>>(hid, dw_w, dw_b, hid2);
    }

    // 8) out = q2 + hid2 @ fc2_w + fc2_b        (24576 x 768 x 192), in-place residual
    {
        dim3 grid(C_ / 128, MQ / 128);
        sgemm_kernel<true><<<grid, 256>>>(hid2, fc2_w, fc2_b, out, out, MQ, C_, HID);
    }
}

// round 2
// speedup vs baseline: 2.8633x; 2.8633x over previous
#include <cuda_runtime.h>
#include <cuda_bf16.h>
#include <math.h>
#include <stdint.h>

// ---------------------------------------------------------------------------
// Problem constants (fixed shapes)
// ---------------------------------------------------------------------------
#define B_      8
#define LQ      3072          // 3*32*32
#define C_      768
#define HF      64
#define WF      64
#define LIN     (HF*WF)       // 4096
#define NH      6
#define NP      4
#define DH      128           // C/NH
#define HID     192
#define HH      32
#define WW      32
#define NIMG    (B_*3)
#define EPSLN   1e-6f
#define NOFF    72            // 48 offsets + 24 attn logits

// ---------------------------------------------------------------------------
// Scratch (static device allocations -- allowed)
// ---------------------------------------------------------------------------
__device__ float g_qnorm [(size_t)B_*LQ*C_];
__device__ float g_fnorm [(size_t)B_*LIN*C_];
__device__ float g_value [(size_t)B_*LIN*C_];
__device__ float g_attn  [(size_t)B_*LQ*C_];
__device__ float g_hid   [(size_t)B_*LQ*HID];
__device__ float g_hid2  [(size_t)B_*LQ*HID];
__device__ float g_logits[(size_t)B_*LQ*NOFF];
__device__ float g_cw    [C_*NOFF];
__device__ float g_cb    [NOFF];

// ---------------------------------------------------------------------------
// helpers
// ---------------------------------------------------------------------------
__device__ __forceinline__ float f2tf32(float x) {
    uint32_t u;
    asm("cvt.rna.tf32.f32 %0, %1;" : "=r"(u) : "f"(x));
    return __uint_as_float(u);
}

__device__ __forceinline__ void mma_tf32(float* c, const uint32_t* a, const uint32_t* b) {
    asm volatile(
        "mma.sync.aligned.m16n8k8.row.col.f32.tf32.tf32.f32 "
        "{%0,%1,%2,%3},{%4,%5,%6,%7},{%8,%9},{%0,%1,%2,%3};\n"
        : "+f"(c[0]), "+f"(c[1]), "+f"(c[2]), "+f"(c[3])
        : "r"(a[0]), "r"(a[1]), "r"(a[2]), "r"(a[3]), "r"(b[0]), "r"(b[1]));
}

// ---------------------------------------------------------------------------
// LayerNorm: one block per row of 768, 256 threads
// ---------------------------------------------------------------------------
__global__ void __launch_bounds__(256) ln_kernel(const float* __restrict__ x,
                                                 const float* __restrict__ w,
                                                 const float* __restrict__ b,
                                                 float* __restrict__ y)
{
    int row = blockIdx.x;
    const float* xr = x + (size_t)row * C_;
    float*       yr = y + (size_t)row * C_;
    int t = threadIdx.x;

    float v[3];
    float s = 0.f, ss = 0.f;
#pragma unroll
    for (int i = 0; i < 3; i++) {
        v[i] = xr[t + i * 256];
        s  += v[i];
        ss += v[i] * v[i];
    }
    __shared__ float rs[8], rss[8];
    int lane = t & 31, wid = t >> 5;
#pragma unroll
    for (int o = 16; o > 0; o >>= 1) {
        s  += __shfl_down_sync(0xffffffffu, s,  o);
        ss += __shfl_down_sync(0xffffffffu, ss, o);
    }
    if (lane == 0) { rs[wid] = s; rss[wid] = ss; }
    __syncthreads();
    if (wid == 0) {
        s  = (lane < 8) ? rs[lane]  : 0.f;
        ss = (lane < 8) ? rss[lane] : 0.f;
#pragma unroll
        for (int o = 4; o > 0; o >>= 1) {
            s  += __shfl_down_sync(0xffffffffu, s,  o);
            ss += __shfl_down_sync(0xffffffffu, ss, o);
        }
        if (lane == 0) { rs[0] = s; rss[0] = ss; }
    }
    __syncthreads();
    float mean = rs[0] * (1.f / C_);
    float var  = rss[0] * (1.f / C_) - mean * mean;
    float rstd = rsqrtf(var + EPSLN);
#pragma unroll
    for (int i = 0; i < 3; i++) {
        int c = t + i * 256;
        yr[c] = (v[i] - mean) * rstd * w[c] + b[c];
    }
}

// ---------------------------------------------------------------------------
// tf32 tensor-core GEMM: C = A(MxK) @ B(KxN) + bias(N) [+ res]
// 128x128x16 tiles, 256 threads, 8 warps (2x4), warp tile 64x32, m16n8k8 mma
// Requires: M % 128 == 0, K % 16 == 0, N % 4 == 0. N bounds-checked.
// ---------------------------------------------------------------------------
template<bool ADD_RES>
__global__ void __launch_bounds__(256, 2) mma_gemm(const float* __restrict__ A,
                                                   const float* __restrict__ Bm,
                                                   const float* __restrict__ bias,
                                                   const float* __restrict__ res,
                                                   float* __restrict__ Cm,
                                                   int M, int N, int K)
{
    __shared__ float As[2][16][136];   // [k][m], pitch 136 => conflict-free frags
    __shared__ float Bs[2][16][136];   // [k][n]

    const int tid  = threadIdx.x;
    const int lane = tid & 31;
    const int wid  = tid >> 5;
    const int wm   = wid & 1;          // 0..1 -> 64 rows
    const int wn   = wid >> 1;         // 0..3 -> 32 cols
    const int rowBase = blockIdx.y * 128;
    const int colBase = blockIdx.x * 128;

    float acc[4][4][4];
#pragma unroll
    for (int i = 0; i < 4; i++)
#pragma unroll
        for (int j = 0; j < 4; j++)
#pragma unroll
            for (int r = 0; r < 4; r++) acc[i][j][r] = 0.f;

    // global-load mapping
    const int aRow = tid >> 2;              // 0..63
    const int aK   = (tid & 3) * 4;         // 0,4,8,12
    const int bK   = tid >> 5;              // 0..7
    const int bN   = (tid & 31) * 4;        // 0..124
    const float* Aptr  = A + (size_t)(rowBase + aRow) * K + aK;
    const float* Aptr2 = Aptr + (size_t)64 * K;
    const bool   bOk   = (colBase + bN) < N;
    const float* Bptr  = Bm + (size_t)bK * N + colBase + bN;
    const float* Bptr2 = Bm + (size_t)(bK + 8) * N + colBase + bN;

    const float4 z4 = make_float4(0.f, 0.f, 0.f, 0.f);

    // prologue: tile 0 -> smem[0]
    {
        float4 a0 = *(const float4*)(Aptr);
        float4 a1 = *(const float4*)(Aptr2);
        As[0][aK + 0][aRow] = f2tf32(a0.x); As[0][aK + 1][aRow] = f2tf32(a0.y);
        As[0][aK + 2][aRow] = f2tf32(a0.z); As[0][aK + 3][aRow] = f2tf32(a0.w);
        As[0][aK + 0][aRow + 64] = f2tf32(a1.x); As[0][aK + 1][aRow + 64] = f2tf32(a1.y);
        As[0][aK + 2][aRow + 64] = f2tf32(a1.z); As[0][aK + 3][aRow + 64] = f2tf32(a1.w);
        float4 b0 = bOk ? *(const float4*)(Bptr)  : z4;
        float4 b1 = bOk ? *(const float4*)(Bptr2) : z4;
        Bs[0][bK][bN + 0] = f2tf32(b0.x); Bs[0][bK][bN + 1] = f2tf32(b0.y);
        Bs[0][bK][bN + 2] = f2tf32(b0.z); Bs[0][bK][bN + 3] = f2tf32(b0.w);
        Bs[0][bK + 8][bN + 0] = f2tf32(b1.x); Bs[0][bK + 8][bN + 1] = f2tf32(b1.y);
        Bs[0][bK + 8][bN + 2] = f2tf32(b1.z); Bs[0][bK + 8][bN + 3] = f2tf32(b1.w);
    }
    __syncthreads();

    const int KT = K >> 4;
    for (int kt = 0; kt < KT; kt++) {
        const int buf = kt & 1;
        float4 na0, na1, nb0, nb1;
        const bool more = (kt + 1) < KT;
        if (more) {
            int k0 = (kt + 1) << 4;
            na0 = *(const float4*)(Aptr + k0);
            na1 = *(const float4*)(Aptr2 + k0);
            nb0 = bOk ? *(const float4*)(Bptr  + (size_t)k0 * N) : z4;
            nb1 = bOk ? *(const float4*)(Bptr2 + (size_t)k0 * N) : z4;
        }

        // compute on smem[buf]
#pragma unroll
        for (int ks = 0; ks < 16; ks += 8) {
            uint32_t af[4][4], bf[4][2];
            const int kA = ks + (lane & 3);
            const int mA = (lane >> 2);
#pragma unroll
            for (int mi = 0; mi < 4; mi++) {
                int mb = wm * 64 + mi * 16;
                af[mi][0] = __float_as_uint(As[buf][kA    ][mb + mA]);
                af[mi][1] = __float_as_uint(As[buf][kA    ][mb + 8 + mA]);
                af[mi][2] = __float_as_uint(As[buf][kA + 4][mb + mA]);
                af[mi][3] = __float_as_uint(As[buf][kA + 4][mb + 8 + mA]);
            }
#pragma unroll
            for (int ni = 0; ni < 4; ni++) {
                int nb = wn * 32 + ni * 8;
                bf[ni][0] = __float_as_uint(Bs[buf][kA    ][nb + mA]);
                bf[ni][1] = __float_as_uint(Bs[buf][kA + 4][nb + mA]);
            }
#pragma unroll
            for (int mi = 0; mi < 4; mi++)
#pragma unroll
                for (int ni = 0; ni < 4; ni++)
                    mma_tf32(acc[mi][ni], af[mi], bf[ni]);
        }

        if (more) {
            const int nb_ = buf ^ 1;
            As[nb_][aK + 0][aRow] = f2tf32(na0.x); As[nb_][aK + 1][aRow] = f2tf32(na0.y);
            As[nb_][aK + 2][aRow] = f2tf32(na0.z); As[nb_][aK + 3][aRow] = f2tf32(na0.w);
            As[nb_][aK + 0][aRow + 64] = f2tf32(na1.x); As[nb_][aK + 1][aRow + 64] = f2tf32(na1.y);
            As[nb_][aK + 2][aRow + 64] = f2tf32(na1.z); As[nb_][aK + 3][aRow + 64] = f2tf32(na1.w);
            Bs[nb_][bK][bN + 0] = f2tf32(nb0.x); Bs[nb_][bK][bN + 1] = f2tf32(nb0.y);
            Bs[nb_][bK][bN + 2] = f2tf32(nb0.z); Bs[nb_][bK][bN + 3] = f2tf32(nb0.w);
            Bs[nb_][bK + 8][bN + 0] = f2tf32(nb1.x); Bs[nb_][bK + 8][bN + 1] = f2tf32(nb1.y);
            Bs[nb_][bK + 8][bN + 2] = f2tf32(nb1.z); Bs[nb_][bK + 8][bN + 3] = f2tf32(nb1.w);
        }
        __syncthreads();
    }

    // epilogue
#pragma unroll
    for (int mi = 0; mi < 4; mi++) {
#pragma unroll
        for (int ni = 0; ni < 4; ni++) {
            int r0 = rowBase + wm * 64 + mi * 16 + (lane >> 2);
            int c0 = colBase + wn * 32 + ni * 8 + (lane & 3) * 2;
            if (c0 < N) {
                float b0 = bias[c0], b1 = bias[c0 + 1];
                {
                    float v0 = acc[mi][ni][0] + b0;
                    float v1 = acc[mi][ni][1] + b1;
                    if (ADD_RES) {
                        const float2 rr = *(const float2*)(res + (size_t)r0 * N + c0);
                        v0 += rr.x; v1 += rr.y;
                    }
                    *(float2*)(Cm + (size_t)r0 * N + c0) = make_float2(v0, v1);
                }
                {
                    int r1 = r0 + 8;
                    float v0 = acc[mi][ni][2] + b0;
                    float v1 = acc[mi][ni][3] + b1;
                    if (ADD_RES) {
                        const float2 rr = *(const float2*)(res + (size_t)r1 * N + c0);
                        v0 += rr.x; v1 += rr.y;
                    }
                    *(float2*)(Cm + (size_t)r1 * N + c0) = make_float2(v0, v1);
                }
            }
        }
    }
}

// ---------------------------------------------------------------------------
// concat so_w (768x48) and aw_w (768x24) into cw (768x72); biases into cb
// ---------------------------------------------------------------------------
__global__ void __launch_bounds__(256) concat_w_kernel(const float* __restrict__ so_w,
                                                       const float* __restrict__ so_b,
                                                       const float* __restrict__ aw_w,
                                                       const float* __restrict__ aw_b,
                                                       float* __restrict__ cw,
                                                       float* __restrict__ cb)
{
    int i = blockIdx.x * 256 + threadIdx.x;
    if (i < C_ * NOFF) {
        int k = i / NOFF, j = i % NOFF;
        cw[i] = (j < 48) ? so_w[k * 48 + j] : aw_w[k * 24 + (j - 48)];
    }
    if (i < NOFF) cb[i] = (i < 48) ? so_b[i] : aw_b[i - 48];
}

// ---------------------------------------------------------------------------
// Deform sampling: softmax + bilinear gather. one block per query row,
// 192 threads = 6 heads x 32 lanes, float4 per lane (128 ch/head)
// ---------------------------------------------------------------------------
__global__ void __launch_bounds__(192) deform_kernel(const float* __restrict__ logits,
                                                     const float* __restrict__ ref,
                                                     const float* __restrict__ value,
                                                     float* __restrict__ out)
{
    int row = blockIdx.x;
    int b = row / LQ;
    int tid = threadIdx.x;

    __shared__ float off_s[48];
    __shared__ float aw_s[24];

    if (tid < NOFF) {
        float v = logits[(size_t)row * NOFF + tid];
        if (tid < 48) off_s[tid] = v; else aw_s[tid - 48] = v;
    }
    __syncthreads();

    if (tid < NH) {
        float m = -1e30f;
#pragma unroll
        for (int p = 0; p < NP; p++) m = fmaxf(m, aw_s[tid * NP + p]);
        float e[NP], ssum = 0.f;
#pragma unroll
        for (int p = 0; p < NP; p++) { e[p] = __expf(aw_s[tid * NP + p] - m); ssum += e[p]; }
        float inv = 1.f / ssum;
#pragma unroll
        for (int p = 0; p < NP; p++) aw_s[tid * NP + p] = e[p] * inv;
    }
    __syncthreads();

    float rx = ref[(size_t)row * 2 + 0] * (float)WF - 0.5f;
    float ry = ref[(size_t)row * 2 + 1] * (float)HF - 0.5f;

    int h  = tid >> 5;
    int c4 = (tid & 31) * 4;
    const float* vb = value + (size_t)b * LIN * C_ + h * DH + c4;

    float4 acc = make_float4(0.f, 0.f, 0.f, 0.f);
#pragma unroll
    for (int p = 0; p < NP; p++) {
        float x = rx + off_s[h * 8 + p * 2 + 0];
        float y = ry + off_s[h * 8 + p * 2 + 1];
        float aw = aw_s[h * NP + p];
        float x0f = floorf(x), y0f = floorf(y);
        int   x0 = (int)x0f,  y0 = (int)y0f;
        float wx1 = x - x0f, wy1 = y - y0f;
        float wx0 = 1.f - wx1, wy0 = 1.f - wy1;
#pragma unroll
        for (int cor = 0; cor < 4; cor++) {
            int dy = cor >> 1, dx = cor & 1;
            int xi = x0 + dx, yi = y0 + dy;
            if (xi >= 0 && xi < WF && yi >= 0 && yi < HF) {
                float wgt = aw * (dy ? wy1 : wy0) * (dx ? wx1 : wx0);
                float4 v4 = *(const float4*)(vb + (size_t)(yi * WF + xi) * C_);
                acc.x = fmaf(wgt, v4.x, acc.x);
                acc.y = fmaf(wgt, v4.y, acc.y);
                acc.z = fmaf(wgt, v4.z, acc.z);
                acc.w = fmaf(wgt, v4.w, acc.w);
            }
        }
    }
    *(float4*)(out + (size_t)row * C_ + h * DH + c4) = acc;
}

// ---------------------------------------------------------------------------
// Depthwise 3x3 (SAME) + bias + exact GELU
// ---------------------------------------------------------------------------
__global__ void __launch_bounds__(256) dwconv_gelu_kernel(const float* __restrict__ x,
                                                          const float* __restrict__ w,
                                                          const float* __restrict__ bias,
                                                          float* __restrict__ y)
{
    int e = blockIdx.x * 256 + threadIdx.x;
    const int TOT = NIMG * HH * WW * HID;
    if (e >= TOT) return;
    int ch   = e % HID;
    int rest = e / HID;
    int wc   = rest % WW;
    int hr   = (rest / WW) % HH;
    int img  = rest / (HH * WW);

    const float* xb = x + (size_t)img * HH * WW * HID;
    float acc = bias[ch];
#pragma unroll
    for (int dy = -1; dy <= 1; dy++) {
        int hh = hr + dy;
        if (hh < 0 || hh >= HH) continue;
#pragma unroll
        for (int dx = -1; dx <= 1; dx++) {
            int wwc = wc + dx;
            if (wwc < 0 || wwc >= WW) continue;
            acc = fmaf(xb[(size_t)(hh * WW + wwc) * HID + ch],
                       w[ch * 9 + (dy + 1) * 3 + (dx + 1)], acc);
        }
    }
    float g = 0.5f * acc * (1.f + erff(acc * 0.70710678118654752f));
    y[e] = g;
}

// ---------------------------------------------------------------------------
// launch
// ---------------------------------------------------------------------------
extern "C" void kernel_launch(void* const* d_in, const int* in_sizes, int n_in,
                              void* d_out, int out_size)
{
    const float* query = (const float*)d_in[0];
    const float* ref   = (const float*)d_in[1];
    const float* feat  = (const float*)d_in[2];
    int ws = n_in - 20;
    const float* qn_w  = (const float*)d_in[ws + 0];
    const float* qn_b  = (const float*)d_in[ws + 1];
    const float* fn_w  = (const float*)d_in[ws + 2];
    const float* fn_b  = (const float*)d_in[ws + 3];
    const float* so_w  = (const float*)d_in[ws + 4];
    const float* so_b  = (const float*)d_in[ws + 5];
    const float* aw_w  = (const float*)d_in[ws + 6];
    const float* aw_b  = (const float*)d_in[ws + 7];
    const float* vp_w  = (const float*)d_in[ws + 8];
    const float* vp_b  = (const float*)d_in[ws + 9];
    const float* op_w  = (const float*)d_in[ws + 10];
    const float* op_b  = (const float*)d_in[ws + 11];
    const float* ffn_w = (const float*)d_in[ws + 12];
    const float* ffn_b = (const float*)d_in[ws + 13];
    const float* fc1_w = (const float*)d_in[ws + 14];
    const float* fc1_b = (const float*)d_in[ws + 15];
    const float* dw_w  = (const float*)d_in[ws + 16];
    const float* dw_b  = (const float*)d_in[ws + 17];
    const float* fc2_w = (const float*)d_in[ws + 18];
    const float* fc2_b = (const float*)d_in[ws + 19];

    float* out = (float*)d_out;

    float *qnorm, *fnorm, *value, *attn, *hid, *hid2, *logits, *cw, *cb;
    cudaGetSymbolAddress((void**)&qnorm,  g_qnorm);
    cudaGetSymbolAddress((void**)&fnorm,  g_fnorm);
    cudaGetSymbolAddress((void**)&value,  g_value);
    cudaGetSymbolAddress((void**)&attn,   g_attn);
    cudaGetSymbolAddress((void**)&hid,    g_hid);
    cudaGetSymbolAddress((void**)&hid2,   g_hid2);
    cudaGetSymbolAddress((void**)&logits, g_logits);
    cudaGetSymbolAddress((void**)&cw,     g_cw);
    cudaGetSymbolAddress((void**)&cb,     g_cb);

    const int MQ = B_ * LQ;    // 24576
    const int MF = B_ * LIN;   // 32768

    // 1) LN(query), LN(feat); concat offset/attn weights
    ln_kernel<<<MQ, 256>>>(query, qn_w, qn_b, qnorm);
    ln_kernel<<<MF, 256>>>(feat, fn_w, fn_b, fnorm);
    concat_w_kernel<<<(C_ * NOFF + 255) / 256, 256>>>(so_w, so_b, aw_w, aw_b, cw, cb);

    // 2) logits = LN(q) @ cw + cb           (24576 x 72 x 768)
    {
        dim3 grid(1, MQ / 128);
        mma_gemm<false><<<grid, 256>>>(qnorm, cw, cb, nullptr, logits, MQ, NOFF, C_);
    }

    // 3) value = LN(feat) @ vp_w + vp_b     (32768 x 768 x 768)
    {
        dim3 grid(C_ / 128, MF / 128);
        mma_gemm<false><<<grid, 256>>>(fnorm, vp_w, vp_b, nullptr, value, MF, C_, C_);
    }

    // 4) softmax + bilinear sampling
    deform_kernel<<<MQ, 192>>>(logits, ref, value, attn);

    // 5) q2 = query + attn @ op_w + op_b    -> d_out
    {
        dim3 grid(C_ / 128, MQ / 128);
        mma_gemm<true><<<grid, 256>>>(attn, op_w, op_b, query, out, MQ, C_, C_);
    }

    // 6) LN(q2)
    ln_kernel<<<MQ, 256>>>(out, ffn_w, ffn_b, qnorm);

    // 7) hid = LN(q2) @ fc1_w + fc1_b       (24576 x 192 x 768)
    {
        dim3 grid((HID + 127) / 128, MQ / 128);
        mma_gemm<false><<<grid, 256>>>(qnorm, fc1_w, fc1_b, nullptr, hid, MQ, HID, C_);
    }

    // 8) depthwise 3x3 + bias + GELU
    {
        int tot = NIMG * HH * WW * HID;
        dwconv_gelu_kernel<<<(tot + 255) / 256, 256>>>(hid, dw_w, dw_b, hid2);
    }

    // 9) out = q2 + hid2 @ fc2_w + fc2_b    (24576 x 768 x 192), in-place residual
    {
        dim3 grid(C_ / 128, MQ / 128);
        mma_gemm<true><<<grid, 256>>>(hid2, fc2_w, fc2_b, out, out, MQ, C_, HID);
    }
}